// round 8
// baseline (speedup 1.0000x reference)
#include <cuda_runtime.h>
#include <cuda_bf16.h>
#include <cstdint>
#include <math.h>

// ---------------------------------------------------------------------------
// Binary CNN fully fused. Round 8: register-diet edition.
//  - double fallback isolated in __noinline__ (rare path, own reg frame)
//  - stage D loop inversion (16 accumulators instead of 24 live weights)
//  - packed int2 thresholds, padded/aligned weight tables
//  - __launch_bounds__(128, 10) -> <=51 regs, 10 blocks/SM
// Numerics identical to rounds 5-7 (rel_err == 0.0).
// ---------------------------------------------------------------------------

#define EPSBND 1e-5
#define BAND   1e-3f

// preprocessed weights / params
__device__ float    g_w1s[32 * 9];            // sign(w1) as +-1.0f
__device__ double   g_inv1d[32], g_bz1d[32];  // exact BN params (double)
__device__ double   g_b1d[32];                // conv1 bias (double)
__device__ float2   g_p1[32];                 // fp32 fast path (inv, off)
__device__ __align__(16) unsigned g_wb2[64 * 4];   // [c*4+t], t=3 pad
__device__ int2     g_mt2[64];                // (mu, T)
__device__ __align__(16) unsigned g_wb3[128 * 8];  // [c*8 + 2t + j], 6..7 pad
__device__ int2     g_mt3[128];
__device__ __align__(16) unsigned g_wb4[128 * 6 * 4];  // [c*24 + h*4 + j]
__device__ int2     g_mt4[128];
__device__ unsigned g_wfb[10 * 64];           // [o*64+jw]

__device__ __forceinline__ float bnref(float dv, float bias, float inv, float bz) {
    return __fadd_rn(__fmul_rn(__fadd_rn(dv, bias), inv), bz);
}

__device__ void mk_threshold(float b, float g, float be, float m, float v,
                             int2* mt_out)
{
    float inv = __fmul_rn(g, rsqrtf(__fadd_rn(v, 1e-5f)));
    float bz  = __fsub_rn(be, __fmul_rn(m, inv));
    int mu, T;

    if (inv > 0.0f) {
        int lo = -1025, hi = 1025, ans = 1 << 20;
        while (lo <= hi) {
            int mid = lo + ((hi - lo) >> 1);
            if (bnref((float)mid, b, inv, bz) >= 0.0f) { ans = mid; hi = mid - 1; }
            else lo = mid + 1;
        }
        mu = 1; T = ans;
    } else if (inv < 0.0f) {
        int lo = -1025, hi = 1025, ans = -(1 << 20);
        while (lo <= hi) {
            int mid = lo + ((hi - lo) >> 1);
            if (bnref((float)mid, b, inv, bz) >= 0.0f) { ans = mid; lo = mid + 1; }
            else hi = mid - 1;
        }
        mu = -1; T = -ans;
    } else {
        mu = 0; T = (bz >= 0.0f) ? -(1 << 20) : (1 << 20);
    }
    *mt_out = make_int2(mu, T);
}

__global__ void prep_kernel(
    const float* __restrict__ w1, const float* __restrict__ b1,
    const float* __restrict__ w2, const float* __restrict__ b2,
    const float* __restrict__ w3, const float* __restrict__ b3,
    const float* __restrict__ w4, const float* __restrict__ b4,
    const float* __restrict__ g1, const float* __restrict__ be1,
    const float* __restrict__ m1, const float* __restrict__ v1,
    const float* __restrict__ g2, const float* __restrict__ be2,
    const float* __restrict__ m2, const float* __restrict__ v2,
    const float* __restrict__ g3, const float* __restrict__ be3,
    const float* __restrict__ m3, const float* __restrict__ v3,
    const float* __restrict__ g4, const float* __restrict__ be4,
    const float* __restrict__ m4, const float* __restrict__ v4,
    const float* __restrict__ wf)
{
    int u = blockIdx.x * blockDim.x + threadIdx.x;

    if (u < 288) {                       // sign(w1) as +-1.0f
        g_w1s[u] = (w1[u] >= 0.f) ? 1.f : -1.f;
        return;
    }
    u -= 288;
    if (u < 32) {                        // layer-1 BN params (double + fp32 fold)
        int c = u;
        double inv = (double)g1[c] / sqrt((double)v1[c] + EPSBND);
        double bz  = (double)be1[c] - (double)m1[c] * inv;
        g_inv1d[c] = inv;
        g_bz1d[c]  = bz;
        g_b1d[c]   = (double)b1[c];
        g_p1[c]    = make_float2((float)inv, (float)((double)b1[c] * inv + bz));
        return;
    }
    u -= 32;
    if (u < 320) {                       // integer thresholds, layers 2..4
        if (u < 64)       mk_threshold(b2[u], g2[u], be2[u], m2[u], v2[u], &g_mt2[u]);
        else if (u < 192) { int c = u - 64;
                          mk_threshold(b3[c], g3[c], be3[c], m3[c], v3[c], &g_mt3[c]); }
        else              { int c = u - 192;
                          mk_threshold(b4[c], g4[c], be4[c], m4[c], v4[c], &g_mt4[c]); }
        return;
    }
    u -= 320;
    if (u < 256) {                       // wb2: w2 (64,32,1,3), t=3 pad
        int c = u >> 2, t = u & 3;
        unsigned word = 0;
        if (t < 3)
            for (int i = 0; i < 32; i++)
                word |= (unsigned)(w2[c * 96 + i * 3 + t] >= 0.f) << i;
        g_wb2[u] = word;
        return;
    }
    u -= 256;
    if (u < 1024) {                      // wb3: w3 (128,64,1,3), r=6,7 pad
        int c = u >> 3, r = u & 7;
        unsigned word = 0;
        if (r < 6) {
            int t = r >> 1, j = r & 1;
            for (int i = 0; i < 32; i++) {
                int cin = j * 32 + i;
                word |= (unsigned)(w3[c * 192 + cin * 3 + t] >= 0.f) << i;
            }
        }
        g_wb3[u] = word;
        return;
    }
    u -= 1024;
    if (u < 3072) {                      // wb4: w4 (128,128,6,1)
        int c = u / 24, r = u % 24, h = r >> 2, j = r & 3;
        unsigned word = 0;
        for (int i = 0; i < 32; i++) {
            int cin = j * 32 + i;
            word |= (unsigned)(w4[c * 768 + cin * 6 + h] >= 0.f) << i;
        }
        g_wb4[u] = word;
        return;
    }
    u -= 3072;
    if (u < 640) {                       // wfb: wf (10,2048), k = c*16+w
        int o = u / 64, jw = u % 64;
        unsigned word = 0;
        for (int i = 0; i < 32; i++)
            word |= (unsigned)(wf[o * 2048 + jw * 32 + i] >= 0.f) << i;
        g_wfb[u] = word;
    }
}

// Rare exact path: recompute conv1 pooled-pair sign in double from smem.
// __noinline__ isolates its register frame from the hot kernel body.
__device__ __noinline__ bool conv1_slow(const float* __restrict__ row, int L)
{
    double inv1 = g_inv1d[L], bz1 = g_bz1d[L], bb1 = g_b1d[L];
    double s0 = 0.0, s1 = 0.0;
#pragma unroll
    for (int t = 0; t < 9; t++) {
        double w = (double)g_w1s[L * 9 + t];
        s0 = fma(w, (double)row[t],     s0);
        s1 = fma(w, (double)row[t + 2], s1);
    }
    double y0 = (s0 + bb1) * inv1 + bz1;
    double y1 = (s1 + bb1) * inv1 + bz1;
    return (y0 >= 0.0) || (y1 >= 0.0);
}

// ---------------------------------------------------------------------------
// Main fused kernel: 1 block = 1 sample, 128 threads (4 warps).
// ---------------------------------------------------------------------------
__global__ __launch_bounds__(128, 10)
void bcnn_kernel(const float* __restrict__ x, const float* __restrict__ bf,
                 float* __restrict__ out)
{
    const int b   = blockIdx.x;
    const int tid = threadIdx.x;
    const int W   = tid >> 5;     // warp id
    const int L   = tid & 31;     // lane id

    __shared__ __align__(16) float    xs[6 * 136];   // [6][4 | 128 | 4] padded
    __shared__ __align__(16) unsigned b1s[192];
    __shared__ __align__(16) unsigned b2s[384];
    __shared__ __align__(16) unsigned b3s[384];
    __shared__ __align__(16) unsigned masks[128];
    __shared__ __align__(16) unsigned fcb[64];

    // load sample with zero padding (4 cols each side)
    const float* xb = x + (size_t)b * 768;
    for (int i = tid; i < 768; i += 128) {
        int r = i >> 7, c = i & 127;
        xs[r * 136 + 4 + c] = xb[i];
    }
    if (tid < 48) {
        int r = tid >> 3, j = tid & 7;
        xs[r * 136 + ((j < 4) ? j : (j + 128))] = 0.f;
    }

    // ---- stage A: conv1 + bias + bn + pool(w2) + binarize ----
    float wrf[9];
#pragma unroll
    for (int t = 0; t < 9; t++) wrf[t] = g_w1s[L * 9 + t];
    float2 p1 = g_p1[L];
    __syncthreads();

    for (int pos = W; pos < 192; pos += 4) {
        int h = pos >> 5, wp = pos & 31;
        const float* row = xs + h * 136 + 4 * wp;
        const float4* rv = (const float4*)row;
        float4 v0 = rv[0], v1 = rv[1], v2 = rv[2];
        float xv[12] = {v0.x, v0.y, v0.z, v0.w,
                        v1.x, v1.y, v1.z, v1.w,
                        v2.x, v2.y, v2.z, v2.w};
        float s0 = 0.f, s1 = 0.f;
#pragma unroll
        for (int t = 0; t < 9; t++) {
            s0 = __fmaf_rn(wrf[t], xv[t],     s0);
            s1 = __fmaf_rn(wrf[t], xv[t + 2], s1);
        }
        float ym = fmaxf(__fmaf_rn(s0, p1.x, p1.y), __fmaf_rn(s1, p1.x, p1.y));
        bool bit = (ym >= 0.f);
        if (fabsf(ym) < BAND) bit = conv1_slow(row, L);   // rare exact path
        unsigned word = __ballot_sync(0xffffffffu, bit);
        if (L == 0) b1s[pos] = word;
    }
    __syncthreads();

    // ---- stage B: conv2 (64ch, cin 32, kw 3, pad 1), sliding window ----
    {
        int q = W & 1;                 // channel half, c = q*32 + L
        int c = q * 32 + L;
        uint4 wt = *(const uint4*)&g_wb2[c * 4];   // wt.x/y/z = taps 0/1/2
        int2 mt = g_mt2[c];
        int mu = mt.x, T = mt.y;
        int r0 = 3 * (W >> 1);         // pair 0: rows 0-2, pair 1: rows 3-5
        for (int r = r0; r < r0 + 3; r++) {
            const unsigned* rp = b1s + r * 32;
            unsigned Acur = rp[0], Anext = rp[1];
            {   // w = 0 (2 valid taps)
                int s = __popc(Acur ^ wt.y) + __popc(Anext ^ wt.z);
                unsigned word = __ballot_sync(0xffffffffu, mu * (64 - 2 * s) >= T);
                if (L == 0) b2s[r * 64 + q] = word;
            }
#pragma unroll
            for (int w = 1; w <= 30; w++) {
                unsigned Aprev = Acur; Acur = Anext; Anext = rp[w + 1];
                int s = __popc(Aprev ^ wt.x) + __popc(Acur ^ wt.y)
                      + __popc(Anext ^ wt.z);
                unsigned word = __ballot_sync(0xffffffffu, mu * (96 - 2 * s) >= T);
                if (L == 0) b2s[r * 64 + 2 * w + q] = word;
            }
            {   // w = 31 (2 valid taps)
                int s = __popc(Acur ^ wt.x) + __popc(Anext ^ wt.y);
                unsigned word = __ballot_sync(0xffffffffu, mu * (64 - 2 * s) >= T);
                if (L == 0) b2s[r * 64 + 62 + q] = word;
            }
        }
    }
    __syncthreads();

    // ---- stage C: conv3 (128ch, cin 64, kw 3, pad 1) + pool(w2) ----
    {
        int c = tid;                   // warp W owns channels 32W..32W+31
        uint4 wAB = *(const uint4*)&g_wb3[c * 8];      // w00 w01 w10 w11
        uint2 wC  = *(const uint2*)&g_wb3[c * 8 + 4];  // w20 w21
        int2 mt = g_mt3[c];
        int mu = mt.x, T = mt.y;

        for (int h = 0; h < 6; h++) {
            const unsigned* rp = b2s + h * 64;
#pragma unroll
            for (int wp = 0; wp < 16; wp++) {
                uint4 M = *(const uint4*)(rp + 4 * wp);   // A(2wp), A(2wp+1)
                int s0 = __popc(M.x ^ wAB.z) + __popc(M.y ^ wAB.w)
                       + __popc(M.z ^ wC.x)  + __popc(M.w ^ wC.y);
                int s1 = __popc(M.x ^ wAB.x) + __popc(M.y ^ wAB.y)
                       + __popc(M.z ^ wAB.z) + __popc(M.w ^ wAB.w);
                int d0, d1;
                if (wp > 0) {
                    uint2 P = *(const uint2*)(rp + 4 * wp - 2); // A(2wp-1)
                    s0 += __popc(P.x ^ wAB.x) + __popc(P.y ^ wAB.y);
                    d0 = 192 - 2 * s0;
                } else d0 = 128 - 2 * s0;
                if (wp < 15) {
                    uint2 N = *(const uint2*)(rp + 4 * wp + 4); // A(2wp+2)
                    s1 += __popc(N.x ^ wC.x) + __popc(N.y ^ wC.y);
                    d1 = 192 - 2 * s1;
                } else d1 = 128 - 2 * s1;
                int e0 = mu * d0, e1 = mu * d1;
                unsigned word = __ballot_sync(0xffffffffu, max(e0, e1) >= T);
                if (L == 0) b3s[(h * 16 + wp) * 4 + W] = word;
            }
        }
    }
    __syncthreads();

    // ---- stage D: conv4 (128ch, cin 128, kh 6, no pad), accumulator form ----
    {
        int c = tid;
        int s[16];
#pragma unroll
        for (int w = 0; w < 16; w++) s[w] = 0;
#pragma unroll
        for (int h = 0; h < 6; h++) {
            uint4 wv = *(const uint4*)&g_wb4[c * 24 + h * 4];
#pragma unroll
            for (int w = 0; w < 16; w++) {
                uint4 A = *(const uint4*)&b3s[(h * 16 + w) * 4];
                s[w] += __popc(A.x ^ wv.x) + __popc(A.y ^ wv.y)
                      + __popc(A.z ^ wv.z) + __popc(A.w ^ wv.w);
            }
        }
        int2 mt = g_mt4[c];
        int mu = mt.x, T = mt.y;
        unsigned mask = 0;
#pragma unroll
        for (int w = 0; w < 16; w++)
            mask |= (mu * (768 - 2 * s[w]) >= T) ? (1u << w) : 0u;
        masks[c] = mask;
    }
    __syncthreads();
    // repack to fc bit order: k = c*16 + w; word j = masks[2j] | masks[2j+1]<<16
    if (tid < 64) fcb[tid] = masks[2 * tid] | (masks[2 * tid + 1] << 16);
    __syncthreads();

    // ---- stage E: fc (10 x 2048 binary dot) + bf (exact integer) ----
    for (int o = W; o < 10; o += 4) {
        int s = __popc(fcb[L]      ^ g_wfb[o * 64 + L])
              + __popc(fcb[L + 32] ^ g_wfb[o * 64 + 32 + L]);
        int tot = __reduce_add_sync(0xffffffffu, s);
        if (L == 0) out[(size_t)b * 10 + o] = (float)(2048 - 2 * tot) + bf[o];
    }
}

extern "C" void kernel_launch(void* const* d_in, const int* in_sizes, int n_in,
                              void* d_out, int out_size)
{
    const float* x   = (const float*)d_in[0];
    const float* w1  = (const float*)d_in[1];
    const float* b1  = (const float*)d_in[2];
    const float* w2  = (const float*)d_in[3];
    const float* b2  = (const float*)d_in[4];
    const float* w3  = (const float*)d_in[5];
    const float* b3  = (const float*)d_in[6];
    const float* w4  = (const float*)d_in[7];
    const float* b4  = (const float*)d_in[8];
    const float* g1  = (const float*)d_in[9];
    const float* be1 = (const float*)d_in[10];
    const float* m1  = (const float*)d_in[11];
    const float* v1  = (const float*)d_in[12];
    const float* g2  = (const float*)d_in[13];
    const float* be2 = (const float*)d_in[14];
    const float* m2  = (const float*)d_in[15];
    const float* v2  = (const float*)d_in[16];
    const float* g3  = (const float*)d_in[17];
    const float* be3 = (const float*)d_in[18];
    const float* m3  = (const float*)d_in[19];
    const float* v3  = (const float*)d_in[20];
    const float* g4  = (const float*)d_in[21];
    const float* be4 = (const float*)d_in[22];
    const float* m4  = (const float*)d_in[23];
    const float* v4  = (const float*)d_in[24];
    const float* wf  = (const float*)d_in[25];
    const float* bf  = (const float*)d_in[26];

    int B = in_sizes[0] / 768;

    prep_kernel<<<22, 256>>>(w1, b1, w2, b2, w3, b3, w4, b4,
                             g1, be1, m1, v1, g2, be2, m2, v2,
                             g3, be3, m3, v3, g4, be4, m4, v4, wf);
    bcnn_kernel<<<B, 128>>>(x, bf, (float*)d_out);
}